// round 14
// baseline (speedup 1.0000x reference)
#include <cuda_runtime.h>
#include <math.h>

#define NTOK 196
#define EMBD 256
#define HIDD 1024
#define NH   8
#define DHD  32
#define NB   296
#define NTHR 256
#define NMIR 37

// ---------------- scratch (allocation-free: __device__ globals) ----------------
__device__ float g_part[16][NTOK * EMBD]; // split-K partials (proj / FF2)
__device__ float g_nrm1[2][NTOK * EMBD];  // LN1 outputs (residual base)
__device__ float g_q[2][NH][NTOK * DHD];  // deinterleaved Q  [n][d]
__device__ float g_k[2][NH][DHD * 200];   // deinterleaved K  [d][n] (pad 200)
__device__ float g_v[2][NH][NTOK * DHD];  // deinterleaved V  [n][d]
__device__ float g_attn[2][NTOK * EMBD];  // attention output
__device__ float g_l[2][NTOK * EMBD];     // LN2 outputs
__device__ float g_hid[2][NTOK * HIDD];   // FF hidden (post-GELU)
__device__ unsigned g_cnt1[NMIR * 32];    // per-group arrival counters (128B apart)
__device__ unsigned g_cnt2 = 0;           // top-level counter (37-way)
__device__ unsigned g_mirror[NMIR * 32];  // release mirrors (128B apart)

// ---------------- grid-wide barrier: two-level arrival tree ----------------
// 296 blocks = 37 groups x 8. Arrival: 8-way atomic per group line, then
// 37-way top atomic. Release: 37 mirrored words, 8 spinners each.
__device__ __forceinline__ void gsync()
{
    __syncthreads();
    if (threadIdx.x == 0) {
        unsigned midx = (blockIdx.x >> 3) * 32;
        __threadfence();
        unsigned gen = *(volatile unsigned*)&g_mirror[midx];
        if (atomicAdd(&g_cnt1[midx], 1u) == 7u) {
            g_cnt1[midx] = 0u;
            __threadfence();
            if (atomicAdd(&g_cnt2, 1u) == NMIR - 1u) {
                g_cnt2 = 0u;
                __threadfence();
                #pragma unroll
                for (int i = 0; i < NMIR; i++)
                    *(volatile unsigned*)&g_mirror[i * 32] = gen + 1u;
            } else {
                while (*(volatile unsigned*)&g_mirror[midx] == gen) { }
            }
        } else {
            while (*(volatile unsigned*)&g_mirror[midx] == gen) { }
        }
        __threadfence();
    }
    __syncthreads();
}

// ---------------- packed fp32x2 FMA helpers ----------------
__device__ __forceinline__ void ffma2(unsigned long long& acc,
                                      unsigned long long a, unsigned long long b)
{
    asm("fma.rn.f32x2 %0, %1, %2, %0;" : "+l"(acc) : "l"(a), "l"(b));
}
__device__ __forceinline__ unsigned long long pk2(float x, float y)
{
    unsigned long long r;
    asm("mov.b64 %0, {%1, %2};" : "=l"(r) : "f"(x), "f"(y));
    return r;
}
__device__ __forceinline__ float2 up2(unsigned long long v)
{
    float2 r;
    asm("mov.b64 {%0, %1}, %2;" : "=f"(r.x), "=f"(r.y) : "l"(v));
    return r;
}

// warp-remapped microtile coordinates: 4x8 lanes per warp
__device__ __forceinline__ int mt_ty(int tid)
{
    return (((tid >> 5) & 3) << 2) + ((tid & 31) >> 3);
}
__device__ __forceinline__ int mt_tx(int tid)
{
    return (((tid >> 5) >> 2) << 3) + (tid & 7);
}

// ---------------- 64x64 GEMM mainloop, 4x4 microtile, f32x2 accum -------------
// Double-buffered smem (1 sync per 32-k slab), register prefetch, A stored
// pre-duplicated (no operand-packing MOVs in inner loop).
#define GBUF (32 * 140 + 32 * 68)

__device__ __forceinline__ void gemm_main(
    const float* __restrict__ A, int lda, int M,
    const float* __restrict__ B, int ldb,
    int row0, int col0, int kstart, int klen, float* sm,
    unsigned long long (&acc)[4][2])
{
    int tid = threadIdx.x;
    int tx = mt_tx(tid), ty = mt_ty(tid);

    #pragma unroll
    for (int i = 0; i < 4; i++) {
        acc[i][0] = 0ull; acc[i][1] = 0ull;
    }

    int ar = tid >> 2, ak = (tid & 3) * 4;
    bool avalid = (row0 + ar) < M;
    const float* Arow = A + (row0 + ar) * lda + kstart + ak;
    int brow = tid >> 4, bcol = (tid & 15) * 4;
    const float* Brow = B + (kstart + brow) * ldb + col0 + bcol;

    float4 av0 = make_float4(0.f, 0.f, 0.f, 0.f), av1 = av0;
    if (avalid) {
        av0 = *(const float4*)Arow;
        av1 = *(const float4*)(Arow + 16);
    }
    float4 bv0 = *(const float4*)Brow;
    float4 bv1 = *(const float4*)(Brow + 16 * ldb);

    int nbuf = 0;
    for (int k0 = 0; k0 < klen; k0 += 32) {
        float* base = sm + nbuf * GBUF;
        float (*As2)[140] = (float(*)[140])base;
        float (*Bs)[68]   = (float(*)[68])(base + 32 * 140);

        *(float2*)&As2[ak + 0][ar * 2]  = make_float2(av0.x, av0.x);
        *(float2*)&As2[ak + 1][ar * 2]  = make_float2(av0.y, av0.y);
        *(float2*)&As2[ak + 2][ar * 2]  = make_float2(av0.z, av0.z);
        *(float2*)&As2[ak + 3][ar * 2]  = make_float2(av0.w, av0.w);
        *(float2*)&As2[ak + 16][ar * 2] = make_float2(av1.x, av1.x);
        *(float2*)&As2[ak + 17][ar * 2] = make_float2(av1.y, av1.y);
        *(float2*)&As2[ak + 18][ar * 2] = make_float2(av1.z, av1.z);
        *(float2*)&As2[ak + 19][ar * 2] = make_float2(av1.w, av1.w);
        *(float4*)&Bs[brow][bcol]      = bv0;
        *(float4*)&Bs[brow + 16][bcol] = bv1;
        __syncthreads();

        if (k0 + 32 < klen) {
            if (avalid) {
                av0 = *(const float4*)(Arow + k0 + 32);
                av1 = *(const float4*)(Arow + k0 + 48);
            }
            bv0 = *(const float4*)(Brow + (k0 + 32) * ldb);
            bv1 = *(const float4*)(Brow + (k0 + 48) * ldb);
        }

        #pragma unroll
        for (int k = 0; k < 32; k++) {
            ulonglong2 aa01 = *(ulonglong2*)&As2[k][ty * 8];
            ulonglong2 aa23 = *(ulonglong2*)&As2[k][ty * 8 + 4];
            ulonglong2 b    = *(ulonglong2*)&Bs[k][tx * 4];
            ffma2(acc[0][0], aa01.x, b.x); ffma2(acc[0][1], aa01.x, b.y);
            ffma2(acc[1][0], aa01.y, b.x); ffma2(acc[1][1], aa01.y, b.y);
            ffma2(acc[2][0], aa23.x, b.x); ffma2(acc[2][1], aa23.x, b.y);
            ffma2(acc[3][0], aa23.y, b.x); ffma2(acc[3][1], aa23.y, b.y);
        }
        nbuf ^= 1;
    }
}

// unpack one acc row into 4 floats
__device__ __forceinline__ void unpack_row(unsigned long long (&acc)[4][2],
                                           int i, float* v)
{
    float2 v0 = up2(acc[i][0]), v1 = up2(acc[i][1]);
    v[0] = v0.x; v[1] = v0.y; v[2] = v1.x; v[3] = v1.y;
}

// ---------------- block LayerNorm over 256-elem row (256 threads) -------------
__device__ __forceinline__ float ln_norm(float v, float w, float b, float* red)
{
    int tid = threadIdx.x;
    float t = v;
    #pragma unroll
    for (int off = 16; off; off >>= 1) t += __shfl_xor_sync(0xffffffffu, t, off);
    __syncthreads();
    if ((tid & 31) == 0) red[tid >> 5] = t;
    __syncthreads();
    float mean = (red[0] + red[1] + red[2] + red[3] +
                  red[4] + red[5] + red[6] + red[7]) * (1.0f / EMBD);
    float d = v - mean;
    t = d * d;
    #pragma unroll
    for (int off = 16; off; off >>= 1) t += __shfl_xor_sync(0xffffffffu, t, off);
    __syncthreads();
    if ((tid & 31) == 0) red[tid >> 5] = t;
    __syncthreads();
    float var = (red[0] + red[1] + red[2] + red[3] +
                 red[4] + red[5] + red[6] + red[7]) * (1.0f / EMBD);
    return d * rsqrtf(var + 1e-5f) * w + b;
}

// ---------------- attention smem layout (floats) ----------------
#define A_KS 0
#define A_VS (32 * 200)
#define A_SS (A_VS + NTOK * DHD)
#define A_QS (A_SS + 32 * 200)
#define A_IV (A_QS + 32 * 32)
#define SMEM_FLOATS (A_IV + 32)
#define SMEM_BYTES  (SMEM_FLOATS * 4)

__device__ void attn_tile(int qt, int h, int s, float* buf)
{
    float (*Ks)[200] = (float(*)[200])(buf + A_KS);
    float (*Vs)[DHD] = (float(*)[DHD])(buf + A_VS);
    float (*Ss)[200] = (float(*)[200])(buf + A_SS);
    float (*Qs)[DHD] = (float(*)[DHD])(buf + A_QS);
    float* inv = buf + A_IV;
    int tid = threadIdx.x;

    const float* gk = g_k[1 - s][h];
    const float* gv = g_v[1 - s][h];
    const float* gq = g_q[s][h];

    for (int i = tid; i < 32 * 50; i += NTHR)
        ((float4*)(buf + A_KS))[i] = ((const float4*)gk)[i];
    for (int i = tid; i < NTOK * 8; i += NTHR)
        ((float4*)(buf + A_VS))[i] = ((const float4*)gv)[i];
    for (int i = tid; i < 32 * 8; i += NTHR) {
        int q = i >> 3, d4 = (i & 7) << 2;
        int qg = qt * 32 + q;
        float4 v = make_float4(0.f, 0.f, 0.f, 0.f);
        if (qg < NTOK) v = *(const float4*)&gq[qg * DHD + d4];
        *(float4*)&Qs[q][d4] = v;
    }
    __syncthreads();

    // scores: f32x2 accumulation; 1/16 scale folded into q registers
    {
        int q = tid >> 3, g = tid & 7;
        float qr[32];
        #pragma unroll
        for (int d = 0; d < 32; d++) qr[d] = Qs[q][d] * 0.0625f;
        #pragma unroll
        for (int kk = 0; kk < 7; kk++) {
            int j0 = g * 4 + kk * 32;
            if (j0 >= NTOK) break;
            unsigned long long a01 = 0ull, a23 = 0ull;
            #pragma unroll
            for (int d = 0; d < 32; d++) {
                unsigned long long aq = pk2(qr[d], qr[d]);
                ulonglong2 kv = *(ulonglong2*)&Ks[d][j0];
                ffma2(a01, aq, kv.x);
                ffma2(a23, aq, kv.y);
            }
            float2 r01 = up2(a01), r23 = up2(a23);
            *(float4*)&Ss[q][j0] = make_float4(r01.x, r01.y, r23.x, r23.y);
        }
    }
    __syncthreads();

    // softmax
    {
        int w = tid >> 5, lane = tid & 31;
        for (int r = 0; r < 4; r++) {
            int q = w * 4 + r;
            float m = -1e30f;
            for (int j = lane; j < NTOK; j += 32) m = fmaxf(m, Ss[q][j]);
            #pragma unroll
            for (int off = 16; off; off >>= 1)
                m = fmaxf(m, __shfl_xor_sync(0xffffffffu, m, off));
            float sum = 0.f;
            for (int j = lane; j < NTOK; j += 32) {
                float e = __expf(Ss[q][j] - m);
                Ss[q][j] = e;
                sum += e;
            }
            #pragma unroll
            for (int off = 16; off; off >>= 1)
                sum += __shfl_xor_sync(0xffffffffu, sum, off);
            if (lane == 0) inv[q] = 1.0f / sum;
        }
    }
    __syncthreads();

    // PV: f32x2 accumulation, p-pairs loaded as float2
    {
        int q = tid >> 3, d0 = (tid & 7) * 4;
        unsigned long long acc01 = 0ull, acc23 = 0ull;
        for (int j = 0; j < NTOK; j += 2) {
            float2 pp = *(float2*)&Ss[q][j];
            unsigned long long p0 = pk2(pp.x, pp.x);
            unsigned long long p1 = pk2(pp.y, pp.y);
            ulonglong2 v0 = *(ulonglong2*)&Vs[j][d0];
            ulonglong2 v1 = *(ulonglong2*)&Vs[j + 1][d0];
            ffma2(acc01, p0, v0.x); ffma2(acc23, p0, v0.y);
            ffma2(acc01, p1, v1.x); ffma2(acc23, p1, v1.y);
        }
        float iv = inv[q];
        float2 r01 = up2(acc01), r23 = up2(acc23);
        float4 o = make_float4(r01.x * iv, r01.y * iv, r23.x * iv, r23.y * iv);
        int qg = qt * 32 + q;
        if (qg < NTOK)
            *(float4*)&g_attn[s][qg * EMBD + h * DHD + d0] = o;
    }
}

// ---------------- fused persistent kernel ----------------
struct Params {
    const float *vis, *ir;
    const float *ln1w[2], *ln1b[2], *ln2w[2], *ln2b[2];
    const float *Wqkv[2], *bqkv[2], *Wp[2], *bp[2];
    const float *W1[2], *b1[2], *W2[2], *b2[2];
    float* out;
};

__global__ void __launch_bounds__(NTHR, 2) fused(Params p)
{
    extern __shared__ float sm[];
    int b = blockIdx.x;
    int tid = threadIdx.x;
    int tx = mt_tx(tid), ty = mt_ty(tid);
    unsigned long long acc[4][2];

    // ---- S0: QKV GEMM K=256 (96 items, 64x64) w/ fused bias + deinterleave,
    //          LN1 on the remaining 200 blocks ----
    if (b < 96) {
        int t = b;
        int nt = t % 12; t /= 12;
        int mt = t % 4; t /= 4;
        int s = t;
        int row0 = mt * 64, col0 = nt * 64;
        gemm_main(s ? p.ir : p.vis, EMBD, NTOK, p.Wqkv[s], 768,
                  row0, col0, 0, 256, sm, acc);
        const float* bq = p.bqkv[s];
        #pragma unroll
        for (int i = 0; i < 4; i++) {
            int n = row0 + ty * 4 + i;
            if (n < NTOK) {
                float v[4];
                unpack_row(acc, i, v);
                #pragma unroll
                for (int j = 0; j < 4; j++) {
                    int c = col0 + tx * 4 + j;
                    float val = v[j] + bq[c];
                    int hd = c / 3, t3 = c - hd * 3;
                    int h = hd >> 5, d = hd & 31;
                    if (t3 == 0)      g_q[s][h][n * DHD + d] = val;
                    else if (t3 == 1) g_k[s][h][d * 200 + n] = val;
                    else              g_v[s][h][n * DHD + d] = val;
                }
            }
        }
    } else {
        for (int r = b - 96; r < 2 * NTOK; r += NB - 96) {
            int s = r >= NTOK;
            int n = s ? r - NTOK : r;
            float v = (s ? p.ir : p.vis)[n * EMBD + tid];
            g_nrm1[s][n * EMBD + tid] =
                ln_norm(v, p.ln1w[s][tid], p.ln1b[s][tid], sm);
        }
    }
    gsync();

    // ---- S1: cross attention (112 items) ----
    if (b < 112) {
        int t = b;
        int qt = t % 7; t /= 7;
        int h = t % 8;
        int s = t / 8;
        attn_tile(qt, h, s, sm);
    }
    gsync();

    // ---- S2: proj split-K=4 partial GEMMs (128 items, 64x64, K=64) ----
    if (b < 128) {
        int t = b;
        int nt = t & 3; t >>= 2;
        int mt = t & 3; t >>= 2;
        int s = t & 1, ks = t >> 1;
        int row0 = mt * 64, col0 = nt * 64;
        gemm_main(g_attn[s], EMBD, NTOK, p.Wp[s], EMBD,
                  row0, col0, ks * 64, 64, sm, acc);
        float* Cp = g_part[ks * 2 + s];
        #pragma unroll
        for (int i = 0; i < 4; i++) {
            int r = row0 + ty * 4 + i;
            if (r < NTOK) {
                float v[4];
                unpack_row(acc, i, v);
                *(float4*)&Cp[r * EMBD + col0 + tx * 4] = *(float4*)&v[0];
            }
        }
    }
    gsync();

    // ---- S3: proj reduce + bias + residual + LN2 ----
    for (int r = b; r < 2 * NTOK; r += NB) {
        int s = r >= NTOK;
        int n = s ? r - NTOK : r;
        int idx = n * EMBD + tid;
        float v = g_part[s][idx] + g_part[2 + s][idx] +
                  g_part[4 + s][idx] + g_part[6 + s][idx] +
                  p.bp[s][tid] + g_nrm1[s][idx];
        g_l[s][idx] = ln_norm(v, p.ln2w[s][tid], p.ln2b[s][tid], sm);
    }
    gsync();

    // ---- S4: FF1 GEMM K=256 (128 items, 64x64) w/ fused bias + exact GELU ----
    if (b < 128) {
        int t = b;
        int nt = t & 15; t >>= 4;
        int mt = t & 3; t >>= 2;
        int s = t;
        int row0 = mt * 64, col0 = nt * 64;
        gemm_main(g_l[s], EMBD, NTOK, p.W1[s], HIDD,
                  row0, col0, 0, 256, sm, acc);
        const float* b1 = p.b1[s];
        #pragma unroll
        for (int i = 0; i < 4; i++) {
            int r = row0 + ty * 4 + i;
            if (r < NTOK) {
                float v[4];
                unpack_row(acc, i, v);
                #pragma unroll
                for (int j = 0; j < 4; j++) {
                    float x = v[j] + b1[col0 + tx * 4 + j];
                    v[j] = 0.5f * x * (1.0f + erff(x * 0.70710678118654752f));
                }
                *(float4*)&g_hid[s][r * HIDD + col0 + tx * 4] = *(float4*)&v[0];
            }
        }
    }
    gsync();

    // ---- S5: FF2 split-K=8 partial GEMMs (256 items, 64x64, K=128) ----
    if (b < 256) {
        int t = b;
        int nt = t & 3; t >>= 2;
        int mt = t & 3; t >>= 2;
        int s = t & 1, ks = t >> 1;      // ks 0..7
        int row0 = mt * 64, col0 = nt * 64;
        gemm_main(g_hid[s], HIDD, NTOK, p.W2[s], EMBD,
                  row0, col0, ks * 128, 128, sm, acc);
        float* Cp = g_part[ks * 2 + s];
        #pragma unroll
        for (int i = 0; i < 4; i++) {
            int r = row0 + ty * 4 + i;
            if (r < NTOK) {
                float v[4];
                unpack_row(acc, i, v);
                *(float4*)&Cp[r * EMBD + col0 + tx * 4] = *(float4*)&v[0];
            }
        }
    }
    gsync();

    // ---- S6: FF2 reduce + bias + residual + pixel-shuffle to d_out ----
    for (int r = b; r < 2 * NTOK; r += NB) {
        int s = r >= NTOK;
        int n = s ? r - NTOK : r;
        int idx = n * EMBD + tid;
        float v = 0.f;
        #pragma unroll
        for (int ks = 0; ks < 8; ks++) v += g_part[ks * 2 + s][idx];
        v += p.b2[s][tid] + g_l[s][idx];
        int i = n / 14, j = n % 14;
        int pp = tid >> 4, q = tid & 15;
        int ch = s ? 0 : 1;
        p.out[ch * 50176 + pp * 3136 + q * 196 + i * 14 + j] = v;
    }
}

// ---------------- launch ----------------
extern "C" void kernel_launch(void* const* d_in, const int* in_sizes, int n_in,
                              void* d_out, int out_size)
{
    Params pr;
    pr.vis = (const float*)d_in[0];
    pr.ir  = (const float*)d_in[1];
    pr.ln1w[0] = (const float*)d_in[2];  pr.ln1b[0] = (const float*)d_in[3];
    pr.ln1w[1] = (const float*)d_in[4];  pr.ln1b[1] = (const float*)d_in[5];
    pr.ln2w[0] = (const float*)d_in[6];  pr.ln2b[0] = (const float*)d_in[7];
    pr.ln2w[1] = (const float*)d_in[8];  pr.ln2b[1] = (const float*)d_in[9];
    pr.Wqkv[0] = (const float*)d_in[10]; pr.bqkv[0] = (const float*)d_in[11];
    pr.Wqkv[1] = (const float*)d_in[12]; pr.bqkv[1] = (const float*)d_in[13];
    pr.Wp[0]   = (const float*)d_in[14]; pr.bp[0]   = (const float*)d_in[15];
    pr.Wp[1]   = (const float*)d_in[16]; pr.bp[1]   = (const float*)d_in[17];
    pr.W1[0]   = (const float*)d_in[18]; pr.b1[0]   = (const float*)d_in[19];
    pr.W2[0]   = (const float*)d_in[20]; pr.b2[0]   = (const float*)d_in[21];
    pr.W1[1]   = (const float*)d_in[22]; pr.b1[1]   = (const float*)d_in[23];
    pr.W2[1]   = (const float*)d_in[24]; pr.b2[1]   = (const float*)d_in[25];
    pr.out = (float*)d_out;

    cudaFuncSetAttribute(fused, cudaFuncAttributeMaxDynamicSharedMemorySize,
                         SMEM_BYTES);
    fused<<<NB, NTHR, SMEM_BYTES>>>(pr);
}

// round 16
// speedup vs baseline: 1.1408x; 1.1408x over previous
#include <cuda_runtime.h>
#include <math.h>

#define NTOK 196
#define EMBD 256
#define HIDD 1024
#define NH   8
#define DHD  32
#define NTHR 256

// ---------------- scratch (allocation-free: __device__ globals) ----------------
__device__ float g_part[16][NTOK * EMBD]; // split-K partials (proj / FF2)
__device__ float g_nrm1[2][NTOK * EMBD];  // LN1 outputs (residual base)
__device__ float g_q[2][NH][NTOK * DHD];  // deinterleaved Q  [n][d]
__device__ float g_k[2][NH][DHD * 200];   // deinterleaved K  [d][n] (pad 200)
__device__ float g_v[2][NH][NTOK * DHD];  // deinterleaved V  [n][d]
__device__ float g_attn[2][NTOK * EMBD];  // attention output
__device__ float g_l[2][NTOK * EMBD];     // LN2 outputs
__device__ float g_hid[2][NTOK * HIDD];   // FF hidden (post-GELU)

// ---------------- packed fp32x2 FMA helpers ----------------
__device__ __forceinline__ void ffma2(unsigned long long& acc,
                                      unsigned long long a, unsigned long long b)
{
    asm("fma.rn.f32x2 %0, %1, %2, %0;" : "+l"(acc) : "l"(a), "l"(b));
}
__device__ __forceinline__ unsigned long long pk2(float x, float y)
{
    unsigned long long r;
    asm("mov.b64 %0, {%1, %2};" : "=l"(r) : "f"(x), "f"(y));
    return r;
}
__device__ __forceinline__ float2 up2(unsigned long long v)
{
    float2 r;
    asm("mov.b64 {%0, %1}, %2;" : "=f"(r.x), "=f"(r.y) : "l"(v));
    return r;
}

// warp-remapped microtile coordinates: 4x8 lanes per warp
__device__ __forceinline__ int mt_ty(int tid)
{
    return (((tid >> 5) & 3) << 2) + ((tid & 31) >> 3);
}
__device__ __forceinline__ int mt_tx(int tid)
{
    return (((tid >> 5) >> 2) << 3) + (tid & 7);
}

// ---------------- 64x64 GEMM mainloop, 4x4 microtile, f32x2 accum -------------
// Double-buffered smem (1 sync per 32-k slab), register prefetch, A stored
// pre-duplicated (no operand-packing MOVs in inner loop).
#define GBUF (32 * 140 + 32 * 68)
#define GEMM_SMEM_BYTES (2 * GBUF * 4)

__device__ __forceinline__ void gemm_main(
    const float* __restrict__ A, int lda, int M,
    const float* __restrict__ B, int ldb,
    int row0, int col0, int kstart, int klen, float* sm,
    unsigned long long (&acc)[4][2])
{
    int tid = threadIdx.x;
    int tx = mt_tx(tid), ty = mt_ty(tid);

    #pragma unroll
    for (int i = 0; i < 4; i++) {
        acc[i][0] = 0ull; acc[i][1] = 0ull;
    }

    int ar = tid >> 2, ak = (tid & 3) * 4;
    bool avalid = (row0 + ar) < M;
    const float* Arow = A + (row0 + ar) * lda + kstart + ak;
    int brow = tid >> 4, bcol = (tid & 15) * 4;
    const float* Brow = B + (kstart + brow) * ldb + col0 + bcol;

    float4 av0 = make_float4(0.f, 0.f, 0.f, 0.f), av1 = av0;
    if (avalid) {
        av0 = *(const float4*)Arow;
        av1 = *(const float4*)(Arow + 16);
    }
    float4 bv0 = *(const float4*)Brow;
    float4 bv1 = *(const float4*)(Brow + 16 * ldb);

    int nbuf = 0;
    for (int k0 = 0; k0 < klen; k0 += 32) {
        float* base = sm + nbuf * GBUF;
        float (*As2)[140] = (float(*)[140])base;
        float (*Bs)[68]   = (float(*)[68])(base + 32 * 140);

        *(float2*)&As2[ak + 0][ar * 2]  = make_float2(av0.x, av0.x);
        *(float2*)&As2[ak + 1][ar * 2]  = make_float2(av0.y, av0.y);
        *(float2*)&As2[ak + 2][ar * 2]  = make_float2(av0.z, av0.z);
        *(float2*)&As2[ak + 3][ar * 2]  = make_float2(av0.w, av0.w);
        *(float2*)&As2[ak + 16][ar * 2] = make_float2(av1.x, av1.x);
        *(float2*)&As2[ak + 17][ar * 2] = make_float2(av1.y, av1.y);
        *(float2*)&As2[ak + 18][ar * 2] = make_float2(av1.z, av1.z);
        *(float2*)&As2[ak + 19][ar * 2] = make_float2(av1.w, av1.w);
        *(float4*)&Bs[brow][bcol]      = bv0;
        *(float4*)&Bs[brow + 16][bcol] = bv1;
        __syncthreads();

        if (k0 + 32 < klen) {
            if (avalid) {
                av0 = *(const float4*)(Arow + k0 + 32);
                av1 = *(const float4*)(Arow + k0 + 48);
            }
            bv0 = *(const float4*)(Brow + (k0 + 32) * ldb);
            bv1 = *(const float4*)(Brow + (k0 + 48) * ldb);
        }

        #pragma unroll
        for (int k = 0; k < 32; k++) {
            ulonglong2 aa01 = *(ulonglong2*)&As2[k][ty * 8];
            ulonglong2 aa23 = *(ulonglong2*)&As2[k][ty * 8 + 4];
            ulonglong2 b    = *(ulonglong2*)&Bs[k][tx * 4];
            ffma2(acc[0][0], aa01.x, b.x); ffma2(acc[0][1], aa01.x, b.y);
            ffma2(acc[1][0], aa01.y, b.x); ffma2(acc[1][1], aa01.y, b.y);
            ffma2(acc[2][0], aa23.x, b.x); ffma2(acc[2][1], aa23.x, b.y);
            ffma2(acc[3][0], aa23.y, b.x); ffma2(acc[3][1], aa23.y, b.y);
        }
        nbuf ^= 1;
    }
}

// unpack one acc row into 4 floats
__device__ __forceinline__ void unpack_row(unsigned long long (&acc)[4][2],
                                           int i, float* v)
{
    float2 v0 = up2(acc[i][0]), v1 = up2(acc[i][1]);
    v[0] = v0.x; v[1] = v0.y; v[2] = v1.x; v[3] = v1.y;
}

// ---------------- block LayerNorm over 256-elem row (256 threads) -------------
__device__ __forceinline__ float ln_norm(float v, float w, float b, float* red)
{
    int tid = threadIdx.x;
    float t = v;
    #pragma unroll
    for (int off = 16; off; off >>= 1) t += __shfl_xor_sync(0xffffffffu, t, off);
    __syncthreads();
    if ((tid & 31) == 0) red[tid >> 5] = t;
    __syncthreads();
    float mean = (red[0] + red[1] + red[2] + red[3] +
                  red[4] + red[5] + red[6] + red[7]) * (1.0f / EMBD);
    float d = v - mean;
    t = d * d;
    #pragma unroll
    for (int off = 16; off; off >>= 1) t += __shfl_xor_sync(0xffffffffu, t, off);
    __syncthreads();
    if ((tid & 31) == 0) red[tid >> 5] = t;
    __syncthreads();
    float var = (red[0] + red[1] + red[2] + red[3] +
                 red[4] + red[5] + red[6] + red[7]) * (1.0f / EMBD);
    return d * rsqrtf(var + 1e-5f) * w + b;
}

// ---------------- attention smem layout (floats) ----------------
#define A_KS 0
#define A_VS (32 * 200)
#define A_SS (A_VS + NTOK * DHD)
#define A_QS (A_SS + 32 * 200)
#define A_IV (A_QS + 32 * 32)
#define ATTN_SMEM_BYTES ((A_IV + 32) * 4)

// ---------------- kernels ----------------

// S0: QKV GEMM (96 blocks, fused bias + deinterleave) + LN1 (392 blocks, 1 row)
__global__ void __launch_bounds__(NTHR, 2) k_prep(
    const float* __restrict__ vis, const float* __restrict__ ir,
    const float* __restrict__ Wqkv0, const float* __restrict__ Wqkv1,
    const float* __restrict__ bqkv0, const float* __restrict__ bqkv1,
    const float* __restrict__ ln1w0, const float* __restrict__ ln1b0,
    const float* __restrict__ ln1w1, const float* __restrict__ ln1b1)
{
    extern __shared__ float sm[];
    int b = blockIdx.x;
    int tid = threadIdx.x;

    if (b < 96) {
        int t = b;
        int nt = t % 12; t /= 12;
        int mt = t % 4; t /= 4;
        int s = t;
        int row0 = mt * 64, col0 = nt * 64;
        unsigned long long acc[4][2];
        gemm_main(s ? ir : vis, EMBD, NTOK, s ? Wqkv1 : Wqkv0, 768,
                  row0, col0, 0, 256, sm, acc);
        const float* bq = s ? bqkv1 : bqkv0;
        int tx = mt_tx(tid), ty = mt_ty(tid);
        #pragma unroll
        for (int i = 0; i < 4; i++) {
            int n = row0 + ty * 4 + i;
            if (n < NTOK) {
                float v[4];
                unpack_row(acc, i, v);
                #pragma unroll
                for (int j = 0; j < 4; j++) {
                    int c = col0 + tx * 4 + j;
                    float val = v[j] + bq[c];
                    int hd = c / 3, t3 = c - hd * 3;
                    int h = hd >> 5, d = hd & 31;
                    if (t3 == 0)      g_q[s][h][n * DHD + d] = val;
                    else if (t3 == 1) g_k[s][h][d * 200 + n] = val;
                    else              g_v[s][h][n * DHD + d] = val;
                }
            }
        }
    } else {
        int r = b - 96;                  // 0..391
        int s = r >= NTOK;
        int n = s ? r - NTOK : r;
        float v = (s ? ir : vis)[n * EMBD + tid];
        g_nrm1[s][n * EMBD + tid] =
            ln_norm(v, (s ? ln1w1 : ln1w0)[tid], (s ? ln1b1 : ln1b0)[tid], sm);
    }
}

// S1: cross attention, grid (7, 8, 2)
__global__ void __launch_bounds__(NTHR, 2) k_attn()
{
    extern __shared__ float buf[];
    float (*Ks)[200] = (float(*)[200])(buf + A_KS);
    float (*Vs)[DHD] = (float(*)[DHD])(buf + A_VS);
    float (*Ss)[200] = (float(*)[200])(buf + A_SS);
    float (*Qs)[DHD] = (float(*)[DHD])(buf + A_QS);
    float* inv = buf + A_IV;

    int qt = blockIdx.x, h = blockIdx.y, s = blockIdx.z;
    int tid = threadIdx.x;

    const float* gk = g_k[1 - s][h];
    const float* gv = g_v[1 - s][h];
    const float* gq = g_q[s][h];

    for (int i = tid; i < 32 * 50; i += NTHR)
        ((float4*)(buf + A_KS))[i] = ((const float4*)gk)[i];
    for (int i = tid; i < NTOK * 8; i += NTHR)
        ((float4*)(buf + A_VS))[i] = ((const float4*)gv)[i];
    for (int i = tid; i < 32 * 8; i += NTHR) {
        int q = i >> 3, d4 = (i & 7) << 2;
        int qg = qt * 32 + q;
        float4 v = make_float4(0.f, 0.f, 0.f, 0.f);
        if (qg < NTOK) v = *(const float4*)&gq[qg * DHD + d4];
        *(float4*)&Qs[q][d4] = v;
    }
    __syncthreads();

    // scores: f32x2 accumulation; 1/16 scale folded into q registers
    {
        int q = tid >> 3, g = tid & 7;
        float qr[32];
        #pragma unroll
        for (int d = 0; d < 32; d++) qr[d] = Qs[q][d] * 0.0625f;
        #pragma unroll
        for (int kk = 0; kk < 7; kk++) {
            int j0 = g * 4 + kk * 32;
            if (j0 >= NTOK) break;
            unsigned long long a01 = 0ull, a23 = 0ull;
            #pragma unroll
            for (int d = 0; d < 32; d++) {
                unsigned long long aq = pk2(qr[d], qr[d]);
                ulonglong2 kv = *(ulonglong2*)&Ks[d][j0];
                ffma2(a01, aq, kv.x);
                ffma2(a23, aq, kv.y);
            }
            float2 r01 = up2(a01), r23 = up2(a23);
            *(float4*)&Ss[q][j0] = make_float4(r01.x, r01.y, r23.x, r23.y);
        }
    }
    __syncthreads();

    // softmax
    {
        int w = tid >> 5, lane = tid & 31;
        for (int r = 0; r < 4; r++) {
            int q = w * 4 + r;
            float m = -1e30f;
            for (int j = lane; j < NTOK; j += 32) m = fmaxf(m, Ss[q][j]);
            #pragma unroll
            for (int off = 16; off; off >>= 1)
                m = fmaxf(m, __shfl_xor_sync(0xffffffffu, m, off));
            float sum = 0.f;
            for (int j = lane; j < NTOK; j += 32) {
                float e = __expf(Ss[q][j] - m);
                Ss[q][j] = e;
                sum += e;
            }
            #pragma unroll
            for (int off = 16; off; off >>= 1)
                sum += __shfl_xor_sync(0xffffffffu, sum, off);
            if (lane == 0) inv[q] = 1.0f / sum;
        }
    }
    __syncthreads();

    // PV: f32x2 accumulation
    {
        int q = tid >> 3, d0 = (tid & 7) * 4;
        unsigned long long acc01 = 0ull, acc23 = 0ull;
        for (int j = 0; j < NTOK; j += 2) {
            float2 pp = *(float2*)&Ss[q][j];
            unsigned long long p0 = pk2(pp.x, pp.x);
            unsigned long long p1 = pk2(pp.y, pp.y);
            ulonglong2 v0 = *(ulonglong2*)&Vs[j][d0];
            ulonglong2 v1 = *(ulonglong2*)&Vs[j + 1][d0];
            ffma2(acc01, p0, v0.x); ffma2(acc23, p0, v0.y);
            ffma2(acc01, p1, v1.x); ffma2(acc23, p1, v1.y);
        }
        float iv = inv[q];
        float2 r01 = up2(acc01), r23 = up2(acc23);
        float4 o = make_float4(r01.x * iv, r01.y * iv, r23.x * iv, r23.y * iv);
        int qg = qt * 32 + q;
        if (qg < NTOK)
            *(float4*)&g_attn[s][qg * EMBD + h * DHD + d0] = o;
    }
}

// S2: proj split-K=4 partial GEMMs (128 blocks)
__global__ void __launch_bounds__(NTHR, 2) k_proj(
    const float* __restrict__ Wp0, const float* __restrict__ Wp1)
{
    extern __shared__ float sm[];
    int t = blockIdx.x;
    int tid = threadIdx.x;
    int nt = t & 3; t >>= 2;
    int mt = t & 3; t >>= 2;
    int s = t & 1, ks = t >> 1;
    int row0 = mt * 64, col0 = nt * 64;
    unsigned long long acc[4][2];
    gemm_main(g_attn[s], EMBD, NTOK, s ? Wp1 : Wp0, EMBD,
              row0, col0, ks * 64, 64, sm, acc);
    float* Cp = g_part[ks * 2 + s];
    int tx = mt_tx(tid), ty = mt_ty(tid);
    #pragma unroll
    for (int i = 0; i < 4; i++) {
        int r = row0 + ty * 4 + i;
        if (r < NTOK) {
            float v[4];
            unpack_row(acc, i, v);
            *(float4*)&Cp[r * EMBD + col0 + tx * 4] = *(float4*)&v[0];
        }
    }
}

// S3: proj reduce + bias + residual + LN2 (392 blocks, 1 row each)
__global__ void __launch_bounds__(NTHR, 4) k_ln2(
    const float* __restrict__ bp0, const float* __restrict__ bp1,
    const float* __restrict__ ln2w0, const float* __restrict__ ln2b0,
    const float* __restrict__ ln2w1, const float* __restrict__ ln2b1)
{
    __shared__ float red[8];
    int r = blockIdx.x;
    int tid = threadIdx.x;
    int s = r >= NTOK;
    int n = s ? r - NTOK : r;
    int idx = n * EMBD + tid;
    float v = g_part[s][idx] + g_part[2 + s][idx] +
              g_part[4 + s][idx] + g_part[6 + s][idx] +
              (s ? bp1 : bp0)[tid] + g_nrm1[s][idx];
    g_l[s][idx] = ln_norm(v, (s ? ln2w1 : ln2w0)[tid],
                          (s ? ln2b1 : ln2b0)[tid], red);
}

// S4: FF1 GEMM K=256 (128 blocks) w/ fused bias + exact GELU
__global__ void __launch_bounds__(NTHR, 2) k_ff1(
    const float* __restrict__ W10, const float* __restrict__ W11,
    const float* __restrict__ b10, const float* __restrict__ b11)
{
    extern __shared__ float sm[];
    int t = blockIdx.x;
    int tid = threadIdx.x;
    int nt = t & 15; t >>= 4;
    int mt = t & 3; t >>= 2;
    int s = t;
    int row0 = mt * 64, col0 = nt * 64;
    unsigned long long acc[4][2];
    gemm_main(g_l[s], EMBD, NTOK, s ? W11 : W10, HIDD,
              row0, col0, 0, 256, sm, acc);
    const float* b1 = s ? b11 : b10;
    int tx = mt_tx(tid), ty = mt_ty(tid);
    #pragma unroll
    for (int i = 0; i < 4; i++) {
        int r = row0 + ty * 4 + i;
        if (r < NTOK) {
            float v[4];
            unpack_row(acc, i, v);
            #pragma unroll
            for (int j = 0; j < 4; j++) {
                float x = v[j] + b1[col0 + tx * 4 + j];
                v[j] = 0.5f * x * (1.0f + erff(x * 0.70710678118654752f));
            }
            *(float4*)&g_hid[s][r * HIDD + col0 + tx * 4] = *(float4*)&v[0];
        }
    }
}

// S5: FF2 split-K=8 partial GEMMs (256 blocks)
__global__ void __launch_bounds__(NTHR, 2) k_ff2(
    const float* __restrict__ W20, const float* __restrict__ W21)
{
    extern __shared__ float sm[];
    int t = blockIdx.x;
    int tid = threadIdx.x;
    int nt = t & 3; t >>= 2;
    int mt = t & 3; t >>= 2;
    int s = t & 1, ks = t >> 1;          // ks 0..7
    int row0 = mt * 64, col0 = nt * 64;
    unsigned long long acc[4][2];
    gemm_main(g_hid[s], HIDD, NTOK, s ? W21 : W20, EMBD,
              row0, col0, ks * 128, 128, sm, acc);
    float* Cp = g_part[ks * 2 + s];
    int tx = mt_tx(tid), ty = mt_ty(tid);
    #pragma unroll
    for (int i = 0; i < 4; i++) {
        int r = row0 + ty * 4 + i;
        if (r < NTOK) {
            float v[4];
            unpack_row(acc, i, v);
            *(float4*)&Cp[r * EMBD + col0 + tx * 4] = *(float4*)&v[0];
        }
    }
}

// S6: FF2 reduce + bias + residual + pixel-shuffle to d_out (392 blocks)
__global__ void __launch_bounds__(NTHR, 4) k_out(
    const float* __restrict__ b20, const float* __restrict__ b21,
    float* __restrict__ out)
{
    int r = blockIdx.x;
    int tid = threadIdx.x;
    int s = r >= NTOK;
    int n = s ? r - NTOK : r;
    int idx = n * EMBD + tid;
    float v = 0.f;
    #pragma unroll
    for (int ks = 0; ks < 8; ks++) v += g_part[ks * 2 + s][idx];
    v += (s ? b21 : b20)[tid] + g_l[s][idx];
    int i = n / 14, j = n % 14;
    int pp = tid >> 4, q = tid & 15;
    int ch = s ? 0 : 1;
    out[ch * 50176 + pp * 3136 + q * 196 + i * 14 + j] = v;
}

// ---------------- launch ----------------
extern "C" void kernel_launch(void* const* d_in, const int* in_sizes, int n_in,
                              void* d_out, int out_size)
{
    const float* vis    = (const float*)d_in[0];
    const float* ir     = (const float*)d_in[1];
    const float* ln1w0  = (const float*)d_in[2];
    const float* ln1b0  = (const float*)d_in[3];
    const float* ln1w1  = (const float*)d_in[4];
    const float* ln1b1  = (const float*)d_in[5];
    const float* ln2w0  = (const float*)d_in[6];
    const float* ln2b0  = (const float*)d_in[7];
    const float* ln2w1  = (const float*)d_in[8];
    const float* ln2b1  = (const float*)d_in[9];
    const float* Wqkv0  = (const float*)d_in[10];
    const float* bqkv0  = (const float*)d_in[11];
    const float* Wqkv1  = (const float*)d_in[12];
    const float* bqkv1  = (const float*)d_in[13];
    const float* Wp0    = (const float*)d_in[14];
    const float* bp0    = (const float*)d_in[15];
    const float* Wp1    = (const float*)d_in[16];
    const float* bp1    = (const float*)d_in[17];
    const float* W10    = (const float*)d_in[18];
    const float* b10    = (const float*)d_in[19];
    const float* W20    = (const float*)d_in[20];
    const float* b20    = (const float*)d_in[21];
    const float* W11    = (const float*)d_in[22];
    const float* b11    = (const float*)d_in[23];
    const float* W21    = (const float*)d_in[24];
    const float* b21    = (const float*)d_in[25];

    static int attr_done = 0;
    if (!attr_done) {
        cudaFuncSetAttribute(k_prep, cudaFuncAttributeMaxDynamicSharedMemorySize,
                             GEMM_SMEM_BYTES);
        cudaFuncSetAttribute(k_attn, cudaFuncAttributeMaxDynamicSharedMemorySize,
                             ATTN_SMEM_BYTES);
        cudaFuncSetAttribute(k_proj, cudaFuncAttributeMaxDynamicSharedMemorySize,
                             GEMM_SMEM_BYTES);
        cudaFuncSetAttribute(k_ff1, cudaFuncAttributeMaxDynamicSharedMemorySize,
                             GEMM_SMEM_BYTES);
        cudaFuncSetAttribute(k_ff2, cudaFuncAttributeMaxDynamicSharedMemorySize,
                             GEMM_SMEM_BYTES);
        attr_done = 1;
    }

    k_prep<<<488, NTHR, GEMM_SMEM_BYTES>>>(vis, ir, Wqkv0, Wqkv1, bqkv0, bqkv1,
                                           ln1w0, ln1b0, ln1w1, ln1b1);
    k_attn<<<dim3(7, NH, 2), NTHR, ATTN_SMEM_BYTES>>>();
    k_proj<<<128, NTHR, GEMM_SMEM_BYTES>>>(Wp0, Wp1);
    k_ln2<<<2 * NTOK, NTHR>>>(bp0, bp1, ln2w0, ln2b0, ln2w1, ln2b1);
    k_ff1<<<128, NTHR, GEMM_SMEM_BYTES>>>(W10, W11, b10, b11);
    k_ff2<<<256, NTHR, GEMM_SMEM_BYTES>>>(W20, W21);
    k_out<<<2 * NTOK, NTHR>>>(b20, b21, (float*)d_out);
}